// round 12
// baseline (speedup 1.0000x reference)
#include <cuda_runtime.h>
#include <cuda_fp16.h>
#include <math.h>
#include <stdint.h>

// ---------------- problem sizes ----------------
#define BSZ   8
#define NSZ   128
#define TSZ   2048
#define FSZ   32
#define LAGS  5
#define HID   64
#define TT    4              // timesteps per block tile
#define NCHUNK 8             // j-chunks of 16
#define JC    16
#define NTHREADS 256

// ---------------- smem layout (in __half units) ----------------
// stage s at s*ST:  A5 [5][128][SA=24] (15360) + Bx [256][SB=24] (6144) = 21504
// W [64][WS=40] at 43008 halfs; bias 64 floats after
#define SA 24
#define SB 24
#define WS 40
#define A5_LAG (128 * SA)              // 3072 halfs
#define ST 21504
#define ST_BYTES (ST * 2)              // 43008
#define OFF_BX 15360                   // within stage
#define OFF_W  (2 * ST)                // 43008 halfs
#define OFF_BIAS_BYTES ((OFF_W + 64 * WS) * 2)   // 91136
#define SMEM_BYTES (OFF_BIAS_BYTES + 256)        // 91392

#define GRP (16 * SB * 2)              // bytes per 16-row B group (768)

__device__ uint4 g_A_h[81920];   // pre-converted fp16 A: 8*5*128*128 halfs

__device__ __forceinline__ uint32_t packh2(float lo, float hi) {
    uint32_t r;
    asm("cvt.rn.f16x2.f32 %0, %1, %2;" : "=r"(r) : "f"(hi), "f"(lo));
    return r;
}

#define LDSM_X4(r0, r1, r2, r3, addr) \
    asm volatile("ldmatrix.sync.aligned.m8n8.x4.shared.b16 {%0,%1,%2,%3}, [%4];" \
        : "=r"(r0), "=r"(r1), "=r"(r2), "=r"(r3) : "r"(addr))

#define CP_ASYNC16(dst, src) \
    asm volatile("cp.async.ca.shared.global [%0], [%1], 16;" :: "r"(dst), "l"(src))

__device__ __forceinline__ void mma_f16(float* d, uint32_t a0, uint32_t a1,
                                        uint32_t a2, uint32_t a3,
                                        uint32_t b0, uint32_t b1) {
    asm volatile(
        "mma.sync.aligned.m16n8k16.row.col.f32.f16.f16.f32 "
        "{%0,%1,%2,%3}, {%4,%5,%6,%7}, {%8,%9}, {%0,%1,%2,%3};"
        : "+f"(d[0]), "+f"(d[1]), "+f"(d[2]), "+f"(d[3])
        : "r"(a0), "r"(a1), "r"(a2), "r"(a3), "r"(b0), "r"(b1));
}

// Packed-fp16 A&S-7.1.26 erf core, fp32 combine (validated in R11).
__device__ __forceinline__ float2 gelu2(float v0, float v1) {
    const __half2 hA   = __float2half2_rn(0.3275911f);
    const __half2 hONE = __float2half2_rn(1.0f);
    const __half2 hC1  = __float2half2_rn(0.254829592f);
    const __half2 hC2  = __float2half2_rn(-0.284496736f);
    const __half2 hC3  = __float2half2_rn(1.421413741f);
    const __half2 hC4  = __float2half2_rn(-1.453152027f);
    const __half2 hC5  = __float2half2_rn(1.061405429f);
    float z0 = fabsf(v0) * 0.70710678118654752440f;
    float z1 = fabsf(v1) * 0.70710678118654752440f;
    __half2 zh = __floats2half2_rn(z0, z1);
    __half2 t  = h2rcp(__hfma2(hA, zh, hONE));
    __half2 p  = __hfma2(hC5, t, hC4);
    p = __hfma2(p, t, hC3);
    p = __hfma2(p, t, hC2);
    p = __hfma2(p, t, hC1);
    p = __hmul2(p, t);
    __half2 e  = h2exp(__hneg2(__hmul2(zh, zh)));
    __half2 er = __hfma2(__hneg2(p), e, hONE);
    float2 ef = __half22float2(er);
    float h0 = 0.5f * v0, h1 = 0.5f * v1;
    float2 r;
    r.x = fmaf(copysignf(ef.x, v0), h0, h0);
    r.y = fmaf(copysignf(ef.y, v1), h1, h1);
    return r;
}

__device__ __forceinline__ uint32_t smem_u32(const void* p) {
    uint32_t a;
    asm("{ .reg .u64 t; cvta.to.shared.u64 t, %1; cvt.u32.u64 %0, t; }" : "=r"(a) : "l"(p));
    return a;
}

// ---------------- prepass: A fp32 -> fp16 ----------------
__global__ void pggcn_prep(const float* __restrict__ A) {
    int i = blockIdx.x * 256 + threadIdx.x;
    float2 v = ((const float2*)A)[i];
    ((__half2*)g_A_h)[i] = __floats2half2_rn(v.x, v.y);
}

// ---------------- main fused kernel ----------------
__global__ __launch_bounds__(NTHREADS, 2)
void pggcn_main(const float* __restrict__ x,     // [B,N,T,F]
                const float* __restrict__ W,     // [HID,F]
                const float* __restrict__ bias,  // [HID]
                float* __restrict__ out)         // [B,N,T,HID]
{
    extern __shared__ __half smh[];
    const uint32_t sbase = smem_u32(smh);

    const int tid = threadIdx.x;
    const int wid = tid >> 5;
    const int lid = tid & 31;
    const int lq  = lid >> 2;
    const int lr  = lid & 3;
    const int b   = blockIdx.y;
    const int t0  = blockIdx.x * TT;

    const int m_base = (wid & 3) * 32;   // 4m x 2n warp grid
    const int n_base = (wid >> 2) * 64;

    const int la_row = ((lid >> 3) & 1) * 8 + (lid & 7);
    const int la_k   = (lid >> 4) * 8;
    const int lb_row = ((lid >> 4) & 1) * 8 + (lid & 7);
    const int lb_k   = ((lid >> 3) & 1) * 8;

    // ---- one-time fills: W (fp16) and bias
    {
#pragma unroll
        for (int it = 0; it < 4; it++) {
            int idx = it * NTHREADS + tid;
            int h = idx >> 4, wq = idx & 15;
            uint32_t w = packh2(W[h * FSZ + 2 * wq], W[h * FSZ + 2 * wq + 1]);
            *(uint32_t*)(smh + OFF_W + h * WS + 2 * wq) = w;
        }
        if (tid < HID) ((float*)((char*)smh + OFF_BIAS_BYTES))[tid] = bias[tid];
    }

    float acc[2][8][4];
#pragma unroll
    for (int i = 0; i < 2; i++)
#pragma unroll
        for (int j = 0; j < 8; j++)
#pragma unroll
            for (int k = 0; k < 4; k++) acc[i][j][k] = 0.0f;

    const uint32_t aA = sbase + 2 * ((m_base + la_row) * SA + la_k);
    const uint32_t aB = sbase + 2 * (OFF_BX + (n_base + lb_row) * SB + lb_k);

    // fill roles
    const int cp_i  = tid >> 1;
    const int cp_hh = tid & 1;
    const __half* Ah = (const __half*)g_A_h;
    const int bn  = tid;
    const int btl = bn >> 5;
    const int bf  = bn & 31;
    const int bts = t0 - 4 + btl;
    const size_t RS = (size_t)TSZ * FSZ;
    const float* xbase = x + ((size_t)b * NSZ) * RS + (size_t)(bts < 0 ? 0 : bts) * FSZ + bf;

    // ---- prologue: fill chunk 0 into stage 0
    {
#pragma unroll
        for (int lag = 0; lag < LAGS; lag++) {
            const __half* src = Ah + (((size_t)(b * LAGS + lag) * NSZ) + cp_i) * NSZ
                                   + cp_hh * 8;
            uint32_t dst = sbase + 2 * (lag * A5_LAG + cp_i * SA + cp_hh * 8);
            CP_ASYNC16(dst, src);
        }
        asm volatile("cp.async.commit_group;" ::: "memory");
        float bpf0[16];
        if (bts >= 0) {
#pragma unroll
            for (int p = 0; p < 16; p++) bpf0[p] = xbase[(size_t)p * RS];
        } else {
#pragma unroll
            for (int p = 0; p < 16; p++) bpf0[p] = 0.0f;
        }
        uint4* dst = (uint4*)(smh + OFF_BX + bn * SB);
        dst[0] = make_uint4(packh2(bpf0[0], bpf0[1]),  packh2(bpf0[2], bpf0[3]),
                            packh2(bpf0[4], bpf0[5]),  packh2(bpf0[6], bpf0[7]));
        dst[1] = make_uint4(packh2(bpf0[8], bpf0[9]),  packh2(bpf0[10], bpf0[11]),
                            packh2(bpf0[12], bpf0[13]), packh2(bpf0[14], bpf0[15]));
        asm volatile("cp.async.wait_group 0;" ::: "memory");
    }
    __syncthreads();

    // ---- pipelined main loop (R11 structure + one-ahead B-fragment pipeline) ----
    for (int jc = 0; jc < NCHUNK; jc++) {
        const int cur = jc & 1;
        const int nxt = cur ^ 1;
        const bool more = (jc + 1 < NCHUNK);
        const int j1 = (jc + 1) * JC;
        const uint32_t stB = cur * ST_BYTES;

        // next-chunk A via cp.async
        if (more) {
#pragma unroll
            for (int lag = 0; lag < LAGS; lag++) {
                const __half* src = Ah + (((size_t)(b * LAGS + lag) * NSZ) + cp_i) * NSZ
                                       + j1 + cp_hh * 8;
                uint32_t dst = sbase + nxt * ST_BYTES
                             + 2 * (lag * A5_LAG + cp_i * SA + cp_hh * 8);
                CP_ASYNC16(dst, src);
            }
            asm volatile("cp.async.commit_group;" ::: "memory");
        }

        // B fill phase 0: 8 LDGs (latency hides under lag 0..1 MMAs)
        const float* xb = xbase + (size_t)j1 * RS;
        float bpf[8];
        if (more && bts >= 0) {
#pragma unroll
            for (int p = 0; p < 8; p++) bpf[p] = xb[(size_t)p * RS];
        }

        // ---- compute: lags ascending (same order as R7/R11), B-frag one ahead.
        // group g = lag*4+nf2; addr(g) = bQ + (8 - 2*(g>>2) + (g&3)) * GRP
        const uint32_t bQ = aB + stB;
        uint32_t bb[2][4], a0[4], a1[4];
        LDSM_X4(bb[0][0], bb[0][1], bb[0][2], bb[0][3], bQ + 8 * GRP);   // g=0

#pragma unroll
        for (int lag = 0; lag < LAGS; lag++) {
            const uint32_t aL = aA + stB + lag * (A5_LAG * 2);
            LDSM_X4(a0[0], a0[1], a0[2], a0[3], aL);
            LDSM_X4(a1[0], a1[1], a1[2], a1[3], aL + 16 * SA * 2);
#pragma unroll
            for (int nf2 = 0; nf2 < 4; nf2++) {
                const int g = lag * 4 + nf2;           // compile-time
                const int pcur = g & 1;
                if (g < 19) {
                    const int g1 = g + 1;
                    LDSM_X4(bb[g1 & 1][0], bb[g1 & 1][1], bb[g1 & 1][2], bb[g1 & 1][3],
                            bQ + (8 - 2 * (g1 >> 2) + (g1 & 3)) * GRP);
                }
                mma_f16(acc[0][2 * nf2],     a0[0], a0[1], a0[2], a0[3],
                        bb[pcur][0], bb[pcur][1]);
                mma_f16(acc[0][2 * nf2 + 1], a0[0], a0[1], a0[2], a0[3],
                        bb[pcur][2], bb[pcur][3]);
                mma_f16(acc[1][2 * nf2],     a1[0], a1[1], a1[2], a1[3],
                        bb[pcur][0], bb[pcur][1]);
                mma_f16(acc[1][2 * nf2 + 1], a1[0], a1[1], a1[2], a1[3],
                        bb[pcur][2], bb[pcur][3]);
            }
            // interleave split global B fill at lag boundaries
            if (lag == 1 && more) {
                uint4 w = make_uint4(0u, 0u, 0u, 0u);
                if (bts >= 0)
                    w = make_uint4(packh2(bpf[0], bpf[1]), packh2(bpf[2], bpf[3]),
                                   packh2(bpf[4], bpf[5]), packh2(bpf[6], bpf[7]));
                *(uint4*)(smh + nxt * ST + OFF_BX + bn * SB) = w;
                if (bts >= 0) {
#pragma unroll
                    for (int p = 0; p < 8; p++) bpf[p] = xb[(size_t)(8 + p) * RS];
                }
            }
            if (lag == 3 && more) {
                uint4 w = make_uint4(0u, 0u, 0u, 0u);
                if (bts >= 0)
                    w = make_uint4(packh2(bpf[0], bpf[1]), packh2(bpf[2], bpf[3]),
                                   packh2(bpf[4], bpf[5]), packh2(bpf[6], bpf[7]));
                *(uint4*)(smh + nxt * ST + OFF_BX + bn * SB + 8) = w;
            }
        }

        if (more) {
            asm volatile("cp.async.wait_group 0;" ::: "memory");
            __syncthreads();
        }
    }

    // ---- stage 2 + epilogue: entirely from registers (C-frag == A-frag identity)
    {
        const uint32_t wB = sbase + 2 * (OFF_W + lb_row * WS + lb_k);
        const float* bias_s = (const float*)((char*)smh + OFF_BIAS_BYTES);
        const int tbase = (wid >> 2) * 2;

#pragma unroll
        for (int tg = 0; tg < 2; tg++) {
            uint32_t af[2][2][4];   // [kg][mf][a0..a3]
#pragma unroll
            for (int kg = 0; kg < 2; kg++) {
                const int nfA = tg * 4 + kg * 2;
#pragma unroll
                for (int mf = 0; mf < 2; mf++) {
                    af[kg][mf][0] = packh2(acc[mf][nfA][0],     acc[mf][nfA][1]);
                    af[kg][mf][1] = packh2(acc[mf][nfA][2],     acc[mf][nfA][3]);
                    af[kg][mf][2] = packh2(acc[mf][nfA + 1][0], acc[mf][nfA + 1][1]);
                    af[kg][mf][3] = packh2(acc[mf][nfA + 1][2], acc[mf][nfA + 1][3]);
                }
            }

            // init stage-2 accumulators with bias
            float a2[2][8][4];
#pragma unroll
            for (int ho = 0; ho < 8; ho++) {
                const int h = ho * 8 + 2 * lr;
                const float bx = bias_s[h], by = bias_s[h + 1];
#pragma unroll
                for (int mf = 0; mf < 2; mf++) {
                    a2[mf][ho][0] = bx; a2[mf][ho][1] = by;
                    a2[mf][ho][2] = bx; a2[mf][ho][3] = by;
                }
            }

#pragma unroll
            for (int kg = 0; kg < 2; kg++) {
#pragma unroll
                for (int hq = 0; hq < 4; hq++) {
                    uint32_t wv[4];
                    LDSM_X4(wv[0], wv[1], wv[2], wv[3],
                            wB + hq * 16 * (WS * 2) + kg * 32);
#pragma unroll
                    for (int mf = 0; mf < 2; mf++) {
                        mma_f16(a2[mf][2 * hq],
                                af[kg][mf][0], af[kg][mf][1], af[kg][mf][2], af[kg][mf][3],
                                wv[0], wv[1]);
                        mma_f16(a2[mf][2 * hq + 1],
                                af[kg][mf][0], af[kg][mf][1], af[kg][mf][2], af[kg][mf][3],
                                wv[2], wv[3]);
                    }
                }
            }

            float* outB = out + (((size_t)b * NSZ) * TSZ + (t0 + tbase + tg)) * HID;
#pragma unroll
            for (int mf = 0; mf < 2; mf++) {
#pragma unroll
                for (int ho = 0; ho < 8; ho++) {
                    int r = m_base + mf * 16 + lq;
                    int h = ho * 8 + 2 * lr;
                    float2 o0 = gelu2(a2[mf][ho][0], a2[mf][ho][1]);
                    float2 o1 = gelu2(a2[mf][ho][2], a2[mf][ho][3]);
                    *(float2*)(outB + (size_t)r * (TSZ * HID) + h)       = o0;
                    *(float2*)(outB + (size_t)(r + 8) * (TSZ * HID) + h) = o1;
                }
            }
        }
    }
}

extern "C" void kernel_launch(void* const* d_in, const int* in_sizes, int n_in,
                              void* d_out, int out_size)
{
    const float* x    = (const float*)d_in[0];   // [8,128,2048,32]
    const float* A    = (const float*)d_in[1];   // [8,5,128,128]
    const float* W    = (const float*)d_in[2];   // [64,32]
    const float* bias = (const float*)d_in[3];   // [64]
    float* out = (float*)d_out;                  // [8,128,2048,64]
    (void)in_sizes; (void)n_in; (void)out_size;

    cudaFuncSetAttribute(pggcn_main,
                         cudaFuncAttributeMaxDynamicSharedMemorySize, SMEM_BYTES);

    pggcn_prep<<<1280, 256>>>(A);
    dim3 grid(TSZ / TT, BSZ);   // (512, 8)
    pggcn_main<<<grid, NTHREADS, SMEM_BYTES>>>(x, W, bias, out);
}

// round 13
// speedup vs baseline: 1.0342x; 1.0342x over previous
#include <cuda_runtime.h>
#include <cuda_fp16.h>
#include <math.h>
#include <stdint.h>

// ---------------- problem sizes ----------------
#define BSZ   8
#define NSZ   128
#define TSZ   2048
#define FSZ   32
#define LAGS  5
#define HID   64
#define TT    4              // timesteps per block tile
#define NCHUNK 8             // j-chunks of 16
#define JC    16
#define NTHREADS 256

// ---------------- smem layout (in __half units) ----------------
// stage s at s*ST:  A5 [5][128][SA=24] (15360) + Bx [256][SB=24] (6144) = 21504
// W [64][WS=40] at 43008 halfs; bias 64 floats after
#define SA 24
#define SB 24
#define WS 40
#define A5_LAG (128 * SA)              // 3072 halfs
#define ST 21504
#define ST_BYTES (ST * 2)              // 43008
#define OFF_BX 15360                   // within stage
#define OFF_W  (2 * ST)                // 43008 halfs
#define OFF_BIAS_BYTES ((OFF_W + 64 * WS) * 2)   // 91136
#define SMEM_BYTES (OFF_BIAS_BYTES + 256)        // 91392

#define ALAGB (A5_LAG * 2)             // bytes per A lag block (6144)
#define BGRP2 (32 * SB * 2)            // bytes per 32-row B shift (1536)

__device__ uint4 g_A_h[81920];   // pre-converted fp16 A: 8*5*128*128 halfs

__device__ __forceinline__ uint32_t packh2(float lo, float hi) {
    uint32_t r;
    asm("cvt.rn.f16x2.f32 %0, %1, %2;" : "=r"(r) : "f"(hi), "f"(lo));
    return r;
}

#define LDSM_X4(r0, r1, r2, r3, addr) \
    asm volatile("ldmatrix.sync.aligned.m8n8.x4.shared.b16 {%0,%1,%2,%3}, [%4];" \
        : "=r"(r0), "=r"(r1), "=r"(r2), "=r"(r3) : "r"(addr))

#define CP_ASYNC16(dst, src) \
    asm volatile("cp.async.ca.shared.global [%0], [%1], 16;" :: "r"(dst), "l"(src))

__device__ __forceinline__ void mma_f16(float* d, uint32_t a0, uint32_t a1,
                                        uint32_t a2, uint32_t a3,
                                        uint32_t b0, uint32_t b1) {
    asm volatile(
        "mma.sync.aligned.m16n8k16.row.col.f32.f16.f16.f32 "
        "{%0,%1,%2,%3}, {%4,%5,%6,%7}, {%8,%9}, {%0,%1,%2,%3};"
        : "+f"(d[0]), "+f"(d[1]), "+f"(d[2]), "+f"(d[3])
        : "r"(a0), "r"(a1), "r"(a2), "r"(a3), "r"(b0), "r"(b1));
}

// Packed-fp16 A&S-7.1.26 erf core, fp32 combine (validated in R11).
__device__ __forceinline__ float2 gelu2(float v0, float v1) {
    const __half2 hA   = __float2half2_rn(0.3275911f);
    const __half2 hONE = __float2half2_rn(1.0f);
    const __half2 hC1  = __float2half2_rn(0.254829592f);
    const __half2 hC2  = __float2half2_rn(-0.284496736f);
    const __half2 hC3  = __float2half2_rn(1.421413741f);
    const __half2 hC4  = __float2half2_rn(-1.453152027f);
    const __half2 hC5  = __float2half2_rn(1.061405429f);
    float z0 = fabsf(v0) * 0.70710678118654752440f;
    float z1 = fabsf(v1) * 0.70710678118654752440f;
    __half2 zh = __floats2half2_rn(z0, z1);
    __half2 t  = h2rcp(__hfma2(hA, zh, hONE));
    __half2 p  = __hfma2(hC5, t, hC4);
    p = __hfma2(p, t, hC3);
    p = __hfma2(p, t, hC2);
    p = __hfma2(p, t, hC1);
    p = __hmul2(p, t);
    __half2 e  = h2exp(__hneg2(__hmul2(zh, zh)));
    __half2 er = __hfma2(__hneg2(p), e, hONE);
    float2 ef = __half22float2(er);
    float h0 = 0.5f * v0, h1 = 0.5f * v1;
    float2 r;
    r.x = fmaf(copysignf(ef.x, v0), h0, h0);
    r.y = fmaf(copysignf(ef.y, v1), h1, h1);
    return r;
}

__device__ __forceinline__ uint32_t smem_u32(const void* p) {
    uint32_t a;
    asm("{ .reg .u64 t; cvta.to.shared.u64 t, %1; cvt.u32.u64 %0, t; }" : "=r"(a) : "l"(p));
    return a;
}

// ---------------- prepass: A fp32 -> fp16 ----------------
__global__ void pggcn_prep(const float* __restrict__ A) {
    int i = blockIdx.x * 256 + threadIdx.x;
    float2 v = ((const float2*)A)[i];
    ((__half2*)g_A_h)[i] = __floats2half2_rn(v.x, v.y);
}

// ---------------- main fused kernel ----------------
__global__ __launch_bounds__(NTHREADS, 2)
void pggcn_main(const float* __restrict__ x,     // [B,N,T,F]
                const float* __restrict__ W,     // [HID,F]
                const float* __restrict__ bias,  // [HID]
                float* __restrict__ out)         // [B,N,T,HID]
{
    extern __shared__ __half smh[];
    const uint32_t sbase = smem_u32(smh);

    const int tid = threadIdx.x;
    const int wid = tid >> 5;
    const int lid = tid & 31;
    const int lq  = lid >> 2;
    const int lr  = lid & 3;
    const int b   = blockIdx.y;
    const int t0  = blockIdx.x * TT;

    const int m_base = (wid & 3) * 32;   // 4m x 2n warp grid
    const int n_base = (wid >> 2) * 64;

    const int la_row = ((lid >> 3) & 1) * 8 + (lid & 7);
    const int la_k   = (lid >> 4) * 8;
    const int lb_row = ((lid >> 4) & 1) * 8 + (lid & 7);
    const int lb_k   = ((lid >> 3) & 1) * 8;

    // per-warp starting lag for convoy-breaking rotation (wid in 0..7 -> wid%5)
    const int lag0 = wid - (wid >= 5 ? 5 : 0);

    // ---- one-time fills: W (fp16) and bias
    {
#pragma unroll
        for (int it = 0; it < 4; it++) {
            int idx = it * NTHREADS + tid;
            int h = idx >> 4, wq = idx & 15;
            uint32_t w = packh2(W[h * FSZ + 2 * wq], W[h * FSZ + 2 * wq + 1]);
            *(uint32_t*)(smh + OFF_W + h * WS + 2 * wq) = w;
        }
        if (tid < HID) ((float*)((char*)smh + OFF_BIAS_BYTES))[tid] = bias[tid];
    }

    float acc[2][8][4];
#pragma unroll
    for (int i = 0; i < 2; i++)
#pragma unroll
        for (int j = 0; j < 8; j++)
#pragma unroll
            for (int k = 0; k < 4; k++) acc[i][j][k] = 0.0f;

    const uint32_t aA = sbase + 2 * ((m_base + la_row) * SA + la_k);
    const uint32_t aB = sbase + 2 * (OFF_BX + (n_base + lb_row) * SB + lb_k);

    // fill roles
    const int cp_i  = tid >> 1;
    const int cp_hh = tid & 1;
    const __half* Ah = (const __half*)g_A_h;
    const int bn  = tid;
    const int btl = bn >> 5;
    const int bf  = bn & 31;
    const int bts = t0 - 4 + btl;
    const size_t RS = (size_t)TSZ * FSZ;
    const float* xbase = x + ((size_t)b * NSZ) * RS + (size_t)(bts < 0 ? 0 : bts) * FSZ + bf;

    float bpf[16];

    // ---- prologue: fill chunk 0 into stage 0
    {
#pragma unroll
        for (int lag = 0; lag < LAGS; lag++) {
            const __half* src = Ah + (((size_t)(b * LAGS + lag) * NSZ) + cp_i) * NSZ
                                   + cp_hh * 8;
            uint32_t dst = sbase + 2 * (lag * A5_LAG + cp_i * SA + cp_hh * 8);
            CP_ASYNC16(dst, src);
        }
        asm volatile("cp.async.commit_group;" ::: "memory");
        if (bts >= 0) {
#pragma unroll
            for (int p = 0; p < 16; p++) bpf[p] = xbase[(size_t)p * RS];
        } else {
#pragma unroll
            for (int p = 0; p < 16; p++) bpf[p] = 0.0f;
        }
        uint4* dst = (uint4*)(smh + OFF_BX + bn * SB);
        dst[0] = make_uint4(packh2(bpf[0], bpf[1]),  packh2(bpf[2], bpf[3]),
                            packh2(bpf[4], bpf[5]),  packh2(bpf[6], bpf[7]));
        dst[1] = make_uint4(packh2(bpf[8], bpf[9]),  packh2(bpf[10], bpf[11]),
                            packh2(bpf[12], bpf[13]), packh2(bpf[14], bpf[15]));
        asm volatile("cp.async.wait_group 0;" ::: "memory");
    }
    __syncthreads();

    // ---- pipelined main loop (R11 structure + per-warp lag rotation) ----
    for (int jc = 0; jc < NCHUNK; jc++) {
        const int cur = jc & 1;
        const int nxt = cur ^ 1;
        const bool more = (jc + 1 < NCHUNK);

        if (more) {
            const int j1 = (jc + 1) * JC;
#pragma unroll
            for (int lag = 0; lag < LAGS; lag++) {
                const __half* src = Ah + (((size_t)(b * LAGS + lag) * NSZ) + cp_i) * NSZ
                                       + j1 + cp_hh * 8;
                uint32_t dst = sbase + nxt * ST_BYTES
                             + 2 * (lag * A5_LAG + cp_i * SA + cp_hh * 8);
                CP_ASYNC16(dst, src);
            }
            asm volatile("cp.async.commit_group;" ::: "memory");
            if (bts >= 0) {
                const float* xb = xbase + (size_t)j1 * RS;
#pragma unroll
                for (int p = 0; p < 16; p++) bpf[p] = xb[(size_t)p * RS];
            }
        }

        // compute: lag order rotated per warp -> warps desynchronize after barrier
        const uint32_t stB = cur * ST_BYTES;
        {
            int      al   = lag0;                       // current lag for this warp
            uint32_t aOff = (uint32_t)lag0 * ALAGB;     // al * A lag stride (bytes)
            uint32_t bOff = (uint32_t)(4 - lag0) * BGRP2;
#pragma unroll
            for (int li = 0; li < LAGS; li++) {
                const uint32_t aL = aA + stB + aOff;
                const uint32_t bL = aB + stB + bOff;
                uint32_t a0[4], a1[4];
                LDSM_X4(a0[0], a0[1], a0[2], a0[3], aL);
                LDSM_X4(a1[0], a1[1], a1[2], a1[3], aL + 16 * SA * 2);
#pragma unroll
                for (int nf2 = 0; nf2 < 4; nf2++) {
                    uint32_t bb[4];
                    LDSM_X4(bb[0], bb[1], bb[2], bb[3], bL + nf2 * (16 * SB * 2));
                    mma_f16(acc[0][2 * nf2],     a0[0], a0[1], a0[2], a0[3], bb[0], bb[1]);
                    mma_f16(acc[0][2 * nf2 + 1], a0[0], a0[1], a0[2], a0[3], bb[2], bb[3]);
                    mma_f16(acc[1][2 * nf2],     a1[0], a1[1], a1[2], a1[3], bb[0], bb[1]);
                    mma_f16(acc[1][2 * nf2 + 1], a1[0], a1[1], a1[2], a1[3], bb[2], bb[3]);
                }
                // advance rotated lag (predicated wrap, no branch)
                al++;
                aOff += ALAGB;
                bOff -= BGRP2;
                if (al == LAGS) { al = 0; aOff = 0; bOff = 4 * BGRP2; }
            }
        }

        if (more) {
            uint4* dst = (uint4*)(smh + nxt * ST + OFF_BX + bn * SB);
            if (bts >= 0) {
                dst[0] = make_uint4(packh2(bpf[0], bpf[1]),  packh2(bpf[2], bpf[3]),
                                    packh2(bpf[4], bpf[5]),  packh2(bpf[6], bpf[7]));
                dst[1] = make_uint4(packh2(bpf[8], bpf[9]),  packh2(bpf[10], bpf[11]),
                                    packh2(bpf[12], bpf[13]), packh2(bpf[14], bpf[15]));
            } else {
                dst[0] = make_uint4(0u, 0u, 0u, 0u);
                dst[1] = make_uint4(0u, 0u, 0u, 0u);
            }
            asm volatile("cp.async.wait_group 0;" ::: "memory");
            __syncthreads();
        }
    }

    // ---- stage 2 + epilogue: entirely from registers (C-frag == A-frag identity)
    {
        const uint32_t wB = sbase + 2 * (OFF_W + lb_row * WS + lb_k);
        const float* bias_s = (const float*)((char*)smh + OFF_BIAS_BYTES);
        const int tbase = (wid >> 2) * 2;

#pragma unroll
        for (int tg = 0; tg < 2; tg++) {
            uint32_t af[2][2][4];   // [kg][mf][a0..a3]
#pragma unroll
            for (int kg = 0; kg < 2; kg++) {
                const int nfA = tg * 4 + kg * 2;
#pragma unroll
                for (int mf = 0; mf < 2; mf++) {
                    af[kg][mf][0] = packh2(acc[mf][nfA][0],     acc[mf][nfA][1]);
                    af[kg][mf][1] = packh2(acc[mf][nfA][2],     acc[mf][nfA][3]);
                    af[kg][mf][2] = packh2(acc[mf][nfA + 1][0], acc[mf][nfA + 1][1]);
                    af[kg][mf][3] = packh2(acc[mf][nfA + 1][2], acc[mf][nfA + 1][3]);
                }
            }

            // init stage-2 accumulators with bias
            float a2[2][8][4];
#pragma unroll
            for (int ho = 0; ho < 8; ho++) {
                const int h = ho * 8 + 2 * lr;
                const float bx = bias_s[h], by = bias_s[h + 1];
#pragma unroll
                for (int mf = 0; mf < 2; mf++) {
                    a2[mf][ho][0] = bx; a2[mf][ho][1] = by;
                    a2[mf][ho][2] = bx; a2[mf][ho][3] = by;
                }
            }

#pragma unroll
            for (int kg = 0; kg < 2; kg++) {
#pragma unroll
                for (int hq = 0; hq < 4; hq++) {
                    uint32_t wv[4];
                    LDSM_X4(wv[0], wv[1], wv[2], wv[3],
                            wB + hq * 16 * (WS * 2) + kg * 32);
#pragma unroll
                    for (int mf = 0; mf < 2; mf++) {
                        mma_f16(a2[mf][2 * hq],
                                af[kg][mf][0], af[kg][mf][1], af[kg][mf][2], af[kg][mf][3],
                                wv[0], wv[1]);
                        mma_f16(a2[mf][2 * hq + 1],
                                af[kg][mf][0], af[kg][mf][1], af[kg][mf][2], af[kg][mf][3],
                                wv[2], wv[3]);
                    }
                }
            }

            float* outB = out + (((size_t)b * NSZ) * TSZ + (t0 + tbase + tg)) * HID;
#pragma unroll
            for (int mf = 0; mf < 2; mf++) {
#pragma unroll
                for (int ho = 0; ho < 8; ho++) {
                    int r = m_base + mf * 16 + lq;
                    int h = ho * 8 + 2 * lr;
                    float2 o0 = gelu2(a2[mf][ho][0], a2[mf][ho][1]);
                    float2 o1 = gelu2(a2[mf][ho][2], a2[mf][ho][3]);
                    *(float2*)(outB + (size_t)r * (TSZ * HID) + h)       = o0;
                    *(float2*)(outB + (size_t)(r + 8) * (TSZ * HID) + h) = o1;
                }
            }
        }
    }
}

extern "C" void kernel_launch(void* const* d_in, const int* in_sizes, int n_in,
                              void* d_out, int out_size)
{
    const float* x    = (const float*)d_in[0];   // [8,128,2048,32]
    const float* A    = (const float*)d_in[1];   // [8,5,128,128]
    const float* W    = (const float*)d_in[2];   // [64,32]
    const float* bias = (const float*)d_in[3];   // [64]
    float* out = (float*)d_out;                  // [8,128,2048,64]
    (void)in_sizes; (void)n_in; (void)out_size;

    cudaFuncSetAttribute(pggcn_main,
                         cudaFuncAttributeMaxDynamicSharedMemorySize, SMEM_BYTES);

    pggcn_prep<<<1280, 256>>>(A);
    dim3 grid(TSZ / TT, BSZ);   // (512, 8)
    pggcn_main<<<grid, NTHREADS, SMEM_BYTES>>>(x, W, bias, out);
}

// round 14
// speedup vs baseline: 1.1082x; 1.0716x over previous
#include <cuda_runtime.h>
#include <cuda_fp16.h>
#include <math.h>
#include <stdint.h>

// ---------------- problem sizes ----------------
#define BSZ   8
#define NSZ   128
#define TSZ   2048
#define FSZ   32
#define LAGS  5
#define HID   64
#define TT    8              // timesteps per block tile (N = 256)
#define NCHUNK 8             // j-chunks of 16
#define JC    16
#define NTHREADS 512
#define BROWS 384            // (TT+4)*32 B-tile rows

// ---------------- smem layout (in __half units) ----------------
// stage s at s*ST:  A5 [5][128][SA=24] (15360) + Bx [384][SB=24] (9216) = 24576
// W [64][WS=40] after stages; bias floats after W
#define SA 24
#define SB 24
#define WS 40
#define A5_LAG (128 * SA)              // 3072 halfs
#define OFF_BX 15360                   // within stage
#define ST 24576
#define ST_BYTES (ST * 2)              // 49152
#define OFF_W  (2 * ST)                // 49152 halfs
#define OFF_BIAS_BYTES ((OFF_W + 64 * WS) * 2)   // 103424
#define SMEM_BYTES (OFF_BIAS_BYTES + 256)        // 103680

__device__ uint4 g_A_h[81920];   // pre-converted fp16 A: 8*5*128*128 halfs

__device__ __forceinline__ uint32_t packh2(float lo, float hi) {
    uint32_t r;
    asm("cvt.rn.f16x2.f32 %0, %1, %2;" : "=r"(r) : "f"(hi), "f"(lo));
    return r;
}

#define LDSM_X4(r0, r1, r2, r3, addr) \
    asm volatile("ldmatrix.sync.aligned.m8n8.x4.shared.b16 {%0,%1,%2,%3}, [%4];" \
        : "=r"(r0), "=r"(r1), "=r"(r2), "=r"(r3) : "r"(addr))

#define CP_ASYNC16(dst, src) \
    asm volatile("cp.async.ca.shared.global [%0], [%1], 16;" :: "r"(dst), "l"(src))

__device__ __forceinline__ void mma_f16(float* d, uint32_t a0, uint32_t a1,
                                        uint32_t a2, uint32_t a3,
                                        uint32_t b0, uint32_t b1) {
    asm volatile(
        "mma.sync.aligned.m16n8k16.row.col.f32.f16.f16.f32 "
        "{%0,%1,%2,%3}, {%4,%5,%6,%7}, {%8,%9}, {%0,%1,%2,%3};"
        : "+f"(d[0]), "+f"(d[1]), "+f"(d[2]), "+f"(d[3])
        : "r"(a0), "r"(a1), "r"(a2), "r"(a3), "r"(b0), "r"(b1));
}

// Packed-fp16 A&S-7.1.26 erf core, fp32 combine (validated R11).
__device__ __forceinline__ float2 gelu2(float v0, float v1) {
    const __half2 hA   = __float2half2_rn(0.3275911f);
    const __half2 hONE = __float2half2_rn(1.0f);
    const __half2 hC1  = __float2half2_rn(0.254829592f);
    const __half2 hC2  = __float2half2_rn(-0.284496736f);
    const __half2 hC3  = __float2half2_rn(1.421413741f);
    const __half2 hC4  = __float2half2_rn(-1.453152027f);
    const __half2 hC5  = __float2half2_rn(1.061405429f);
    float z0 = fabsf(v0) * 0.70710678118654752440f;
    float z1 = fabsf(v1) * 0.70710678118654752440f;
    __half2 zh = __floats2half2_rn(z0, z1);
    __half2 t  = h2rcp(__hfma2(hA, zh, hONE));
    __half2 p  = __hfma2(hC5, t, hC4);
    p = __hfma2(p, t, hC3);
    p = __hfma2(p, t, hC2);
    p = __hfma2(p, t, hC1);
    p = __hmul2(p, t);
    __half2 e  = h2exp(__hneg2(__hmul2(zh, zh)));
    __half2 er = __hfma2(__hneg2(p), e, hONE);
    float2 ef = __half22float2(er);
    float h0 = 0.5f * v0, h1 = 0.5f * v1;
    float2 r;
    r.x = fmaf(copysignf(ef.x, v0), h0, h0);
    r.y = fmaf(copysignf(ef.y, v1), h1, h1);
    return r;
}

__device__ __forceinline__ uint32_t smem_u32(const void* p) {
    uint32_t a;
    asm("{ .reg .u64 t; cvta.to.shared.u64 t, %1; cvt.u32.u64 %0, t; }" : "=r"(a) : "l"(p));
    return a;
}

// ---------------- prepass: A fp32 -> fp16 ----------------
__global__ void pggcn_prep(const float* __restrict__ A) {
    int i = blockIdx.x * 256 + threadIdx.x;
    float2 v = ((const float2*)A)[i];
    ((__half2*)g_A_h)[i] = __floats2half2_rn(v.x, v.y);
}

// ---------------- main fused kernel ----------------
__global__ __launch_bounds__(NTHREADS, 1)
void pggcn_main(const float* __restrict__ x,     // [B,N,T,F]
                const float* __restrict__ W,     // [HID,F]
                const float* __restrict__ bias,  // [HID]
                float* __restrict__ out)         // [B,N,T,HID]
{
    extern __shared__ __half smh[];
    const uint32_t sbase = smem_u32(smh);

    const int tid = threadIdx.x;
    const int wid = tid >> 5;    // 0..15
    const int lid = tid & 31;
    const int lq  = lid >> 2;
    const int lr  = lid & 3;
    const int b   = blockIdx.y;
    const int t0  = blockIdx.x * TT;

    const int m_base = (wid & 3) * 32;    // 4m x 4n warp grid
    const int n_base = (wid >> 2) * 64;   // 0,64,128,192

    const int la_row = ((lid >> 3) & 1) * 8 + (lid & 7);
    const int la_k   = (lid >> 4) * 8;
    const int lb_row = ((lid >> 4) & 1) * 8 + (lid & 7);
    const int lb_k   = ((lid >> 3) & 1) * 8;

    // ---- one-time fills: W (fp16) and bias
    {
#pragma unroll
        for (int it = 0; it < 2; it++) {
            int idx = it * NTHREADS + tid;           // 1024 words
            int h = idx >> 4, wq = idx & 15;
            uint32_t w = packh2(W[h * FSZ + 2 * wq], W[h * FSZ + 2 * wq + 1]);
            *(uint32_t*)(smh + OFF_W + h * WS + 2 * wq) = w;
        }
        if (tid < HID) ((float*)((char*)smh + OFF_BIAS_BYTES))[tid] = bias[tid];
    }

    float acc[2][8][4];
#pragma unroll
    for (int i = 0; i < 2; i++)
#pragma unroll
        for (int j = 0; j < 8; j++)
#pragma unroll
            for (int k = 0; k < 4; k++) acc[i][j][k] = 0.0f;

    const uint32_t aA = sbase + 2 * ((m_base + la_row) * SA + la_k);
    const uint32_t aB = sbase + 2 * (OFF_BX + (n_base + lb_row) * SB + lb_k);

    // fill roles
    const __half* Ah = (const __half*)g_A_h;
    // B fill: threads 0..383 each own one row
    const bool bact = (tid < BROWS);
    const int bn  = tid;
    const int btl = bn >> 5;               // 0..11
    const int bf  = bn & 31;
    const int bts = t0 - 4 + btl;
    const size_t RS = (size_t)TSZ * FSZ;
    const float* xbase = x + ((size_t)b * NSZ) * RS + (size_t)(bts < 0 ? 0 : bts) * FSZ + bf;

    float bpf[16];

    // ---- prologue: fill chunk 0 into stage 0
    {
        // A: 1280 cp.asyncs over 512 threads (2.5 each)
#pragma unroll
        for (int it = 0; it < 3; it++) {
            int idx = it * NTHREADS + tid;
            if (idx < 1280) {
                int lag = idx >> 8, r8 = idx & 255;
                int i = r8 >> 1, hh = r8 & 1;
                const __half* src = Ah + (((size_t)(b * LAGS + lag) * NSZ) + i) * NSZ
                                       + hh * 8;
                uint32_t dst = sbase + 2 * (lag * A5_LAG + i * SA + hh * 8);
                CP_ASYNC16(dst, src);
            }
        }
        asm volatile("cp.async.commit_group;" ::: "memory");
        if (bact) {
            if (bts >= 0) {
#pragma unroll
                for (int p = 0; p < 16; p++) bpf[p] = xbase[(size_t)p * RS];
            } else {
#pragma unroll
                for (int p = 0; p < 16; p++) bpf[p] = 0.0f;
            }
            uint4* dst = (uint4*)(smh + OFF_BX + bn * SB);
            dst[0] = make_uint4(packh2(bpf[0], bpf[1]),  packh2(bpf[2], bpf[3]),
                                packh2(bpf[4], bpf[5]),  packh2(bpf[6], bpf[7]));
            dst[1] = make_uint4(packh2(bpf[8], bpf[9]),  packh2(bpf[10], bpf[11]),
                                packh2(bpf[12], bpf[13]), packh2(bpf[14], bpf[15]));
        }
        asm volatile("cp.async.wait_group 0;" ::: "memory");
    }
    __syncthreads();

    // ---- pipelined main loop (R11 per-warp structure, verbatim) ----
    for (int jc = 0; jc < NCHUNK; jc++) {
        const int cur = jc & 1;
        const int nxt = cur ^ 1;
        const bool more = (jc + 1 < NCHUNK);

        if (more) {
            const int j1 = (jc + 1) * JC;
#pragma unroll
            for (int it = 0; it < 3; it++) {
                int idx = it * NTHREADS + tid;
                if (idx < 1280) {
                    int lag = idx >> 8, r8 = idx & 255;
                    int i = r8 >> 1, hh = r8 & 1;
                    const __half* src = Ah + (((size_t)(b * LAGS + lag) * NSZ) + i) * NSZ
                                           + j1 + hh * 8;
                    uint32_t dst = sbase + nxt * ST_BYTES
                                 + 2 * (lag * A5_LAG + i * SA + hh * 8);
                    CP_ASYNC16(dst, src);
                }
            }
            asm volatile("cp.async.commit_group;" ::: "memory");
            if (bact && bts >= 0) {
                const float* xb = xbase + (size_t)j1 * RS;
#pragma unroll
                for (int p = 0; p < 16; p++) bpf[p] = xb[(size_t)p * RS];
            }
        }

        const uint32_t stB = cur * ST_BYTES;
#pragma unroll
        for (int lag = 0; lag < LAGS; lag++) {
            const uint32_t aL = aA + stB + lag * (A5_LAG * 2);
            const uint32_t bL = aB + stB + (4 - lag) * (32 * SB * 2);
            uint32_t a0[4], a1[4];
            LDSM_X4(a0[0], a0[1], a0[2], a0[3], aL);
            LDSM_X4(a1[0], a1[1], a1[2], a1[3], aL + 16 * SA * 2);
#pragma unroll
            for (int nf2 = 0; nf2 < 4; nf2++) {
                uint32_t bb[4];
                LDSM_X4(bb[0], bb[1], bb[2], bb[3], bL + nf2 * (16 * SB * 2));
                mma_f16(acc[0][2 * nf2],     a0[0], a0[1], a0[2], a0[3], bb[0], bb[1]);
                mma_f16(acc[0][2 * nf2 + 1], a0[0], a0[1], a0[2], a0[3], bb[2], bb[3]);
                mma_f16(acc[1][2 * nf2],     a1[0], a1[1], a1[2], a1[3], bb[0], bb[1]);
                mma_f16(acc[1][2 * nf2 + 1], a1[0], a1[1], a1[2], a1[3], bb[2], bb[3]);
            }
        }

        if (more) {
            if (bact) {
                uint4* dst = (uint4*)(smh + nxt * ST + OFF_BX + bn * SB);
                if (bts >= 0) {
                    dst[0] = make_uint4(packh2(bpf[0], bpf[1]),  packh2(bpf[2], bpf[3]),
                                        packh2(bpf[4], bpf[5]),  packh2(bpf[6], bpf[7]));
                    dst[1] = make_uint4(packh2(bpf[8], bpf[9]),  packh2(bpf[10], bpf[11]),
                                        packh2(bpf[12], bpf[13]), packh2(bpf[14], bpf[15]));
                } else {
                    dst[0] = make_uint4(0u, 0u, 0u, 0u);
                    dst[1] = make_uint4(0u, 0u, 0u, 0u);
                }
            }
            asm volatile("cp.async.wait_group 0;" ::: "memory");
            __syncthreads();
        }
    }

    // ---- stage 2 + epilogue: entirely from registers (verbatim R11) ----
    {
        const uint32_t wB = sbase + 2 * (OFF_W + lb_row * WS + lb_k);
        const float* bias_s = (const float*)((char*)smh + OFF_BIAS_BYTES);
        const int tbase = (wid >> 2) * 2;     // 0,2,4,6

#pragma unroll
        for (int tg = 0; tg < 2; tg++) {
            uint32_t af[2][2][4];   // [kg][mf][a0..a3]
#pragma unroll
            for (int kg = 0; kg < 2; kg++) {
                const int nfA = tg * 4 + kg * 2;
#pragma unroll
                for (int mf = 0; mf < 2; mf++) {
                    af[kg][mf][0] = packh2(acc[mf][nfA][0],     acc[mf][nfA][1]);
                    af[kg][mf][1] = packh2(acc[mf][nfA][2],     acc[mf][nfA][3]);
                    af[kg][mf][2] = packh2(acc[mf][nfA + 1][0], acc[mf][nfA + 1][1]);
                    af[kg][mf][3] = packh2(acc[mf][nfA + 1][2], acc[mf][nfA + 1][3]);
                }
            }

            float a2[2][8][4];
#pragma unroll
            for (int ho = 0; ho < 8; ho++) {
                const int h = ho * 8 + 2 * lr;
                const float bx = bias_s[h], by = bias_s[h + 1];
#pragma unroll
                for (int mf = 0; mf < 2; mf++) {
                    a2[mf][ho][0] = bx; a2[mf][ho][1] = by;
                    a2[mf][ho][2] = bx; a2[mf][ho][3] = by;
                }
            }

#pragma unroll
            for (int kg = 0; kg < 2; kg++) {
#pragma unroll
                for (int hq = 0; hq < 4; hq++) {
                    uint32_t wv[4];
                    LDSM_X4(wv[0], wv[1], wv[2], wv[3],
                            wB + hq * 16 * (WS * 2) + kg * 32);
#pragma unroll
                    for (int mf = 0; mf < 2; mf++) {
                        mma_f16(a2[mf][2 * hq],
                                af[kg][mf][0], af[kg][mf][1], af[kg][mf][2], af[kg][mf][3],
                                wv[0], wv[1]);
                        mma_f16(a2[mf][2 * hq + 1],
                                af[kg][mf][0], af[kg][mf][1], af[kg][mf][2], af[kg][mf][3],
                                wv[2], wv[3]);
                    }
                }
            }

            float* outB = out + (((size_t)b * NSZ) * TSZ + (t0 + tbase + tg)) * HID;
#pragma unroll
            for (int mf = 0; mf < 2; mf++) {
#pragma unroll
                for (int ho = 0; ho < 8; ho++) {
                    int r = m_base + mf * 16 + lq;
                    int h = ho * 8 + 2 * lr;
                    float2 o0 = gelu2(a2[mf][ho][0], a2[mf][ho][1]);
                    float2 o1 = gelu2(a2[mf][ho][2], a2[mf][ho][3]);
                    *(float2*)(outB + (size_t)r * (TSZ * HID) + h)       = o0;
                    *(float2*)(outB + (size_t)(r + 8) * (TSZ * HID) + h) = o1;
                }
            }
        }
    }
}

extern "C" void kernel_launch(void* const* d_in, const int* in_sizes, int n_in,
                              void* d_out, int out_size)
{
    const float* x    = (const float*)d_in[0];   // [8,128,2048,32]
    const float* A    = (const float*)d_in[1];   // [8,5,128,128]
    const float* W    = (const float*)d_in[2];   // [64,32]
    const float* bias = (const float*)d_in[3];   // [64]
    float* out = (float*)d_out;                  // [8,128,2048,64]
    (void)in_sizes; (void)n_in; (void)out_size;

    cudaFuncSetAttribute(pggcn_main,
                         cudaFuncAttributeMaxDynamicSharedMemorySize, SMEM_BYTES);

    pggcn_prep<<<1280, 256>>>(A);
    dim3 grid(TSZ / TT, BSZ);   // (256, 8)
    pggcn_main<<<grid, NTHREADS, SMEM_BYTES>>>(x, W, bias, out);
}

// round 15
// speedup vs baseline: 1.1390x; 1.0278x over previous
#include <cuda_runtime.h>
#include <cuda_fp16.h>
#include <math.h>
#include <stdint.h>

// ---------------- problem sizes ----------------
#define BSZ   8
#define NSZ   128
#define TSZ   2048
#define FSZ   32
#define LAGS  5
#define HID   64
#define TT    8              // timesteps per block tile (N = 256)
#define NCHUNK 8             // j-chunks of 16
#define JC    16
#define NTHREADS 512
#define BROWS 384            // (TT+4)*32 B-tile rows

// ---------------- smem layout (in __half units) ----------------
#define SA 24
#define SB 24
#define WS 40
#define A5_LAG (128 * SA)              // 3072 halfs
#define OFF_BX 15360                   // within stage
#define ST 24576
#define ST_BYTES (ST * 2)              // 49152
#define OFF_W  (2 * ST)                // 49152 halfs
#define OFF_BIAS_BYTES ((OFF_W + 64 * WS) * 2)   // 103424
#define OFF_MBAR_BYTES (OFF_BIAS_BYTES + 256)    // 103680
#define SMEM_BYTES (OFF_MBAR_BYTES + 64)         // 103744

__device__ uint4 g_A_h[81920];   // pre-converted fp16 A: 8*5*128*128 halfs

__device__ __forceinline__ uint32_t packh2(float lo, float hi) {
    uint32_t r;
    asm("cvt.rn.f16x2.f32 %0, %1, %2;" : "=r"(r) : "f"(hi), "f"(lo));
    return r;
}

#define LDSM_X4(r0, r1, r2, r3, addr) \
    asm volatile("ldmatrix.sync.aligned.m8n8.x4.shared.b16 {%0,%1,%2,%3}, [%4];" \
        : "=r"(r0), "=r"(r1), "=r"(r2), "=r"(r3) : "r"(addr))

#define CP_ASYNC16(dst, src) \
    asm volatile("cp.async.ca.shared.global [%0], [%1], 16;" :: "r"(dst), "l"(src))

#define MBAR_INIT(addr, cnt) \
    asm volatile("mbarrier.init.shared.b64 [%0], %1;" :: "r"((uint32_t)(addr)), "r"((uint32_t)(cnt)) : "memory")
#define MBAR_ARRIVE(addr) \
    asm volatile("mbarrier.arrive.shared.b64 _, [%0];" :: "r"((uint32_t)(addr)) : "memory")
#define MBAR_WAIT(addr, par) do { \
    uint32_t _m = (uint32_t)(addr); uint32_t _p = (uint32_t)(par); uint32_t _d; \
    asm volatile("{\n\t.reg .pred p;\n\tmbarrier.try_wait.parity.acquire.cta.shared::cta.b64 p, [%1], %2;\n\tselp.b32 %0, 1, 0, p;\n\t}" \
        : "=r"(_d) : "r"(_m), "r"(_p) : "memory"); \
    if (!_d) { \
        asm volatile("{\n\t.reg .pred P1;\n\tWL_%=:\n\tmbarrier.try_wait.parity.acquire.cta.shared::cta.b64 P1, [%0], %1, 0x989680;\n\t@P1 bra.uni WD_%=;\n\tbra.uni WL_%=;\n\tWD_%=:\n\t}" \
            :: "r"(_m), "r"(_p) : "memory"); \
    } } while (0)

__device__ __forceinline__ void mma_f16(float* d, uint32_t a0, uint32_t a1,
                                        uint32_t a2, uint32_t a3,
                                        uint32_t b0, uint32_t b1) {
    asm volatile(
        "mma.sync.aligned.m16n8k16.row.col.f32.f16.f16.f32 "
        "{%0,%1,%2,%3}, {%4,%5,%6,%7}, {%8,%9}, {%0,%1,%2,%3};"
        : "+f"(d[0]), "+f"(d[1]), "+f"(d[2]), "+f"(d[3])
        : "r"(a0), "r"(a1), "r"(a2), "r"(a3), "r"(b0), "r"(b1));
}

// Packed-fp16 A&S-7.1.26 erf core, fp32 combine (validated R11).
__device__ __forceinline__ float2 gelu2(float v0, float v1) {
    const __half2 hA   = __float2half2_rn(0.3275911f);
    const __half2 hONE = __float2half2_rn(1.0f);
    const __half2 hC1  = __float2half2_rn(0.254829592f);
    const __half2 hC2  = __float2half2_rn(-0.284496736f);
    const __half2 hC3  = __float2half2_rn(1.421413741f);
    const __half2 hC4  = __float2half2_rn(-1.453152027f);
    const __half2 hC5  = __float2half2_rn(1.061405429f);
    float z0 = fabsf(v0) * 0.70710678118654752440f;
    float z1 = fabsf(v1) * 0.70710678118654752440f;
    __half2 zh = __floats2half2_rn(z0, z1);
    __half2 t  = h2rcp(__hfma2(hA, zh, hONE));
    __half2 p  = __hfma2(hC5, t, hC4);
    p = __hfma2(p, t, hC3);
    p = __hfma2(p, t, hC2);
    p = __hfma2(p, t, hC1);
    p = __hmul2(p, t);
    __half2 e  = h2exp(__hneg2(__hmul2(zh, zh)));
    __half2 er = __hfma2(__hneg2(p), e, hONE);
    float2 ef = __half22float2(er);
    float h0 = 0.5f * v0, h1 = 0.5f * v1;
    float2 r;
    r.x = fmaf(copysignf(ef.x, v0), h0, h0);
    r.y = fmaf(copysignf(ef.y, v1), h1, h1);
    return r;
}

__device__ __forceinline__ uint32_t smem_u32(const void* p) {
    uint32_t a;
    asm("{ .reg .u64 t; cvta.to.shared.u64 t, %1; cvt.u32.u64 %0, t; }" : "=r"(a) : "l"(p));
    return a;
}

// ---------------- prepass: A fp32 -> fp16 ----------------
__global__ void pggcn_prep(const float* __restrict__ A) {
    int i = blockIdx.x * 256 + threadIdx.x;
    float2 v = ((const float2*)A)[i];
    ((__half2*)g_A_h)[i] = __floats2half2_rn(v.x, v.y);
}

// ---------------- main fused kernel ----------------
__global__ __launch_bounds__(NTHREADS, 1)
void pggcn_main(const float* __restrict__ x,     // [B,N,T,F]
                const float* __restrict__ W,     // [HID,F]
                const float* __restrict__ bias,  // [HID]
                float* __restrict__ out)         // [B,N,T,HID]
{
    extern __shared__ __half smh[];
    const uint32_t sbase = smem_u32(smh);

    const int tid = threadIdx.x;
    const int wid = tid >> 5;    // 0..15
    const int lid = tid & 31;
    const int lq  = lid >> 2;
    const int lr  = lid & 3;
    const int b   = blockIdx.y;
    const int t0  = blockIdx.x * TT;

    const int m_base = (wid & 3) * 32;    // 4m x 4n warp grid
    const int n_base = (wid >> 2) * 64;

    const int la_row = ((lid >> 3) & 1) * 8 + (lid & 7);
    const int la_k   = (lid >> 4) * 8;
    const int lb_row = ((lid >> 4) & 1) * 8 + (lid & 7);
    const int lb_k   = ((lid >> 3) & 1) * 8;

    // mbarriers: free[0], free[1], fill[0], fill[1]
    const uint32_t mb_free = sbase + OFF_MBAR_BYTES;
    const uint32_t mb_fill = sbase + OFF_MBAR_BYTES + 16;

    // ---- one-time fills: W (fp16), bias, mbarrier init
    {
#pragma unroll
        for (int it = 0; it < 2; it++) {
            int idx = it * NTHREADS + tid;
            int h = idx >> 4, wq = idx & 15;
            uint32_t w = packh2(W[h * FSZ + 2 * wq], W[h * FSZ + 2 * wq + 1]);
            *(uint32_t*)(smh + OFF_W + h * WS + 2 * wq) = w;
        }
        if (tid < HID) ((float*)((char*)smh + OFF_BIAS_BYTES))[tid] = bias[tid];
        if (tid == 0) {
            MBAR_INIT(mb_free + 0, 16);
            MBAR_INIT(mb_free + 8, 16);
            MBAR_INIT(mb_fill + 0, 16);
            MBAR_INIT(mb_fill + 8, 16);
        }
    }

    float acc[2][8][4];
#pragma unroll
    for (int i = 0; i < 2; i++)
#pragma unroll
        for (int j = 0; j < 8; j++)
#pragma unroll
            for (int k = 0; k < 4; k++) acc[i][j][k] = 0.0f;

    const uint32_t aA = sbase + 2 * ((m_base + la_row) * SA + la_k);
    const uint32_t aB = sbase + 2 * (OFF_BX + (n_base + lb_row) * SB + lb_k);

    // fill roles
    const __half* Ah = (const __half*)g_A_h;
    const bool bact = (tid < BROWS);
    const int bn  = tid;
    const int btl = bn >> 5;
    const int bf  = bn & 31;
    const int bts = t0 - 4 + btl;
    const size_t RS = (size_t)TSZ * FSZ;
    const float* xbase = x + ((size_t)b * NSZ) * RS + (size_t)(bts < 0 ? 0 : bts) * FSZ + bf;

    float bpf[16];

    // ---- prologue: fill chunk 0 into stage 0, then ONE block barrier
    {
#pragma unroll
        for (int it = 0; it < 3; it++) {
            int idx = it * NTHREADS + tid;
            if (idx < 1280) {
                int lag = idx >> 8, r8 = idx & 255;
                int i = r8 >> 1, hh = r8 & 1;
                const __half* src = Ah + (((size_t)(b * LAGS + lag) * NSZ) + i) * NSZ
                                       + hh * 8;
                uint32_t dst = sbase + 2 * (lag * A5_LAG + i * SA + hh * 8);
                CP_ASYNC16(dst, src);
            }
        }
        asm volatile("cp.async.commit_group;" ::: "memory");
        if (bact) {
            if (bts >= 0) {
#pragma unroll
                for (int p = 0; p < 16; p++) bpf[p] = xbase[(size_t)p * RS];
            } else {
#pragma unroll
                for (int p = 0; p < 16; p++) bpf[p] = 0.0f;
            }
            uint4* dst = (uint4*)(smh + OFF_BX + bn * SB);
            dst[0] = make_uint4(packh2(bpf[0], bpf[1]),  packh2(bpf[2], bpf[3]),
                                packh2(bpf[4], bpf[5]),  packh2(bpf[6], bpf[7]));
            dst[1] = make_uint4(packh2(bpf[8], bpf[9]),  packh2(bpf[10], bpf[11]),
                                packh2(bpf[12], bpf[13]), packh2(bpf[14], bpf[15]));
        }
        asm volatile("cp.async.wait_group 0;" ::: "memory");
    }
    __syncthreads();

    // ---- mbarrier-pipelined main loop: NO block-wide barriers -> warps desync
    for (int jc = 0; jc < NCHUNK; jc++) {
        const int cur = jc & 1;
        const int nxt = cur ^ 1;
        const bool more = (jc + 1 < NCHUNK);
        const int j1 = (jc + 1) * JC;

        // early global B loads for next chunk (registers only, no hazard)
        if (more && bact && bts >= 0) {
            const float* xb = xbase + (size_t)j1 * RS;
#pragma unroll
            for (int p = 0; p < 16; p++) bpf[p] = xb[(size_t)p * RS];
        }

        if (jc >= 1) {
            const uint32_t parw = (uint32_t)(((jc - 1) >> 1) & 1);
            // stage nxt free? (all warps finished compute(jc-1) which used nxt)
            MBAR_WAIT(mb_free + nxt * 8, parw);
            // fill stage nxt with next A while waiting on our own fill barrier
            if (more) {
#pragma unroll
                for (int it = 0; it < 3; it++) {
                    int idx = it * NTHREADS + tid;
                    if (idx < 1280) {
                        int lag = idx >> 8, r8 = idx & 255;
                        int i = r8 >> 1, hh = r8 & 1;
                        const __half* src = Ah + (((size_t)(b * LAGS + lag) * NSZ) + i) * NSZ
                                               + j1 + hh * 8;
                        uint32_t dst = sbase + nxt * ST_BYTES
                                     + 2 * (lag * A5_LAG + i * SA + hh * 8);
                        CP_ASYNC16(dst, src);
                    }
                }
                asm volatile("cp.async.commit_group;" ::: "memory");
            }
            // all fills for chunk jc landed?
            MBAR_WAIT(mb_fill + cur * 8, parw);
        } else if (more) {
            // jc == 0: stage 1 is virgin; just issue fills
#pragma unroll
            for (int it = 0; it < 3; it++) {
                int idx = it * NTHREADS + tid;
                if (idx < 1280) {
                    int lag = idx >> 8, r8 = idx & 255;
                    int i = r8 >> 1, hh = r8 & 1;
                    const __half* src = Ah + (((size_t)(b * LAGS + lag) * NSZ) + i) * NSZ
                                           + j1 + hh * 8;
                    uint32_t dst = sbase + nxt * ST_BYTES
                                 + 2 * (lag * A5_LAG + i * SA + hh * 8);
                    CP_ASYNC16(dst, src);
                }
            }
            asm volatile("cp.async.commit_group;" ::: "memory");
        }

        // ---- compute chunk jc from stage cur (verbatim R14)
        const uint32_t stB = cur * ST_BYTES;
#pragma unroll
        for (int lag = 0; lag < LAGS; lag++) {
            const uint32_t aL = aA + stB + lag * (A5_LAG * 2);
            const uint32_t bL = aB + stB + (4 - lag) * (32 * SB * 2);
            uint32_t a0[4], a1[4];
            LDSM_X4(a0[0], a0[1], a0[2], a0[3], aL);
            LDSM_X4(a1[0], a1[1], a1[2], a1[3], aL + 16 * SA * 2);
#pragma unroll
            for (int nf2 = 0; nf2 < 4; nf2++) {
                uint32_t bb[4];
                LDSM_X4(bb[0], bb[1], bb[2], bb[3], bL + nf2 * (16 * SB * 2));
                mma_f16(acc[0][2 * nf2],     a0[0], a0[1], a0[2], a0[3], bb[0], bb[1]);
                mma_f16(acc[0][2 * nf2 + 1], a0[0], a0[1], a0[2], a0[3], bb[2], bb[3]);
                mma_f16(acc[1][2 * nf2],     a1[0], a1[1], a1[2], a1[3], bb[0], bb[1]);
                mma_f16(acc[1][2 * nf2 + 1], a1[0], a1[1], a1[2], a1[3], bb[2], bb[3]);
            }
        }
        if (lid == 0) MBAR_ARRIVE(mb_free + cur * 8);

        // ---- finish fill of stage nxt: own cp.asyncs + B STS, then signal
        if (more) {
            asm volatile("cp.async.wait_group 0;" ::: "memory");
            if (bact) {
                uint4* dst = (uint4*)(smh + nxt * ST + OFF_BX + bn * SB);
                if (bts >= 0) {
                    dst[0] = make_uint4(packh2(bpf[0], bpf[1]),  packh2(bpf[2], bpf[3]),
                                        packh2(bpf[4], bpf[5]),  packh2(bpf[6], bpf[7]));
                    dst[1] = make_uint4(packh2(bpf[8], bpf[9]),  packh2(bpf[10], bpf[11]),
                                        packh2(bpf[12], bpf[13]), packh2(bpf[14], bpf[15]));
                } else {
                    dst[0] = make_uint4(0u, 0u, 0u, 0u);
                    dst[1] = make_uint4(0u, 0u, 0u, 0u);
                }
            }
            if (lid == 0) MBAR_ARRIVE(mb_fill + nxt * 8);
        }
    }

    // ---- stage 2 + epilogue: entirely from registers (verbatim R14) ----
    {
        const uint32_t wB = sbase + 2 * (OFF_W + lb_row * WS + lb_k);
        const float* bias_s = (const float*)((char*)smh + OFF_BIAS_BYTES);
        const int tbase = (wid >> 2) * 2;

#pragma unroll
        for (int tg = 0; tg < 2; tg++) {
            uint32_t af[2][2][4];
#pragma unroll
            for (int kg = 0; kg < 2; kg++) {
                const int nfA = tg * 4 + kg * 2;
#pragma unroll
                for (int mf = 0; mf < 2; mf++) {
                    af[kg][mf][0] = packh2(acc[mf][nfA][0],     acc[mf][nfA][1]);
                    af[kg][mf][1] = packh2(acc[mf][nfA][2],     acc[mf][nfA][3]);
                    af[kg][mf][2] = packh2(acc[mf][nfA + 1][0], acc[mf][nfA + 1][1]);
                    af[kg][mf][3] = packh2(acc[mf][nfA + 1][2], acc[mf][nfA + 1][3]);
                }
            }

            float a2[2][8][4];
#pragma unroll
            for (int ho = 0; ho < 8; ho++) {
                const int h = ho * 8 + 2 * lr;
                const float bx = bias_s[h], by = bias_s[h + 1];
#pragma unroll
                for (int mf = 0; mf < 2; mf++) {
                    a2[mf][ho][0] = bx; a2[mf][ho][1] = by;
                    a2[mf][ho][2] = bx; a2[mf][ho][3] = by;
                }
            }

#pragma unroll
            for (int kg = 0; kg < 2; kg++) {
#pragma unroll
                for (int hq = 0; hq < 4; hq++) {
                    uint32_t wv[4];
                    LDSM_X4(wv[0], wv[1], wv[2], wv[3],
                            wB + hq * 16 * (WS * 2) + kg * 32);
#pragma unroll
                    for (int mf = 0; mf < 2; mf++) {
                        mma_f16(a2[mf][2 * hq],
                                af[kg][mf][0], af[kg][mf][1], af[kg][mf][2], af[kg][mf][3],
                                wv[0], wv[1]);
                        mma_f16(a2[mf][2 * hq + 1],
                                af[kg][mf][0], af[kg][mf][1], af[kg][mf][2], af[kg][mf][3],
                                wv[2], wv[3]);
                    }
                }
            }

            float* outB = out + (((size_t)b * NSZ) * TSZ + (t0 + tbase + tg)) * HID;
#pragma unroll
            for (int mf = 0; mf < 2; mf++) {
#pragma unroll
                for (int ho = 0; ho < 8; ho++) {
                    int r = m_base + mf * 16 + lq;
                    int h = ho * 8 + 2 * lr;
                    float2 o0 = gelu2(a2[mf][ho][0], a2[mf][ho][1]);
                    float2 o1 = gelu2(a2[mf][ho][2], a2[mf][ho][3]);
                    *(float2*)(outB + (size_t)r * (TSZ * HID) + h)       = o0;
                    *(float2*)(outB + (size_t)(r + 8) * (TSZ * HID) + h) = o1;
                }
            }
        }
    }
}

extern "C" void kernel_launch(void* const* d_in, const int* in_sizes, int n_in,
                              void* d_out, int out_size)
{
    const float* x    = (const float*)d_in[0];   // [8,128,2048,32]
    const float* A    = (const float*)d_in[1];   // [8,5,128,128]
    const float* W    = (const float*)d_in[2];   // [64,32]
    const float* bias = (const float*)d_in[3];   // [64]
    float* out = (float*)d_out;                  // [8,128,2048,64]
    (void)in_sizes; (void)n_in; (void)out_size;

    cudaFuncSetAttribute(pggcn_main,
                         cudaFuncAttributeMaxDynamicSharedMemorySize, SMEM_BYTES);

    pggcn_prep<<<1280, 256>>>(A);
    dim3 grid(TSZ / TT, BSZ);   // (256, 8)
    pggcn_main<<<grid, NTHREADS, SMEM_BYTES>>>(x, W, bias, out);
}

// round 16
// speedup vs baseline: 1.1584x; 1.0170x over previous
#include <cuda_runtime.h>
#include <cuda_fp16.h>
#include <math.h>
#include <stdint.h>

// ---------------- problem sizes ----------------
#define BSZ   8
#define NSZ   128
#define TSZ   2048
#define FSZ   32
#define LAGS  5
#define HID   64
#define TT    8              // timesteps per block tile (N = 256)
#define NCHUNK 8             // j-chunks of 16
#define JC    16
#define NTHREADS 512
#define BROWS 384            // (TT+4)*32 B-tile rows
#define NSTG  3              // pipeline stages

// ---------------- smem layout (in __half units) ----------------
#define SA 24
#define SB 24
#define WS 40
#define A5_LAG (128 * SA)              // 3072 halfs
#define OFF_BX 15360                   // within stage
#define ST 24576
#define ST_BYTES (ST * 2)              // 49152
#define OFF_W  (NSTG * ST)             // 73728 halfs
#define OFF_BIAS_BYTES ((OFF_W + 64 * WS) * 2)   // 152576
#define OFF_MBAR_BYTES (OFF_BIAS_BYTES + 256)    // 152832
#define SMEM_BYTES (OFF_MBAR_BYTES + 96)         // 152928

__device__ uint4 g_A_h[81920];   // pre-converted fp16 A: 8*5*128*128 halfs

__device__ __forceinline__ uint32_t packh2(float lo, float hi) {
    uint32_t r;
    asm("cvt.rn.f16x2.f32 %0, %1, %2;" : "=r"(r) : "f"(hi), "f"(lo));
    return r;
}

#define LDSM_X4(r0, r1, r2, r3, addr) \
    asm volatile("ldmatrix.sync.aligned.m8n8.x4.shared.b16 {%0,%1,%2,%3}, [%4];" \
        : "=r"(r0), "=r"(r1), "=r"(r2), "=r"(r3) : "r"(addr))

#define CP_ASYNC16(dst, src) \
    asm volatile("cp.async.ca.shared.global [%0], [%1], 16;" :: "r"(dst), "l"(src))

#define MBAR_INIT(addr, cnt) \
    asm volatile("mbarrier.init.shared.b64 [%0], %1;" :: "r"((uint32_t)(addr)), "r"((uint32_t)(cnt)) : "memory")
#define MBAR_ARRIVE(addr) \
    asm volatile("mbarrier.arrive.shared.b64 _, [%0];" :: "r"((uint32_t)(addr)) : "memory")
#define MBAR_WAIT(addr, par) do { \
    uint32_t _m = (uint32_t)(addr); uint32_t _p = (uint32_t)(par); uint32_t _d; \
    asm volatile("{\n\t.reg .pred p;\n\tmbarrier.try_wait.parity.acquire.cta.shared::cta.b64 p, [%1], %2;\n\tselp.b32 %0, 1, 0, p;\n\t}" \
        : "=r"(_d) : "r"(_m), "r"(_p) : "memory"); \
    if (!_d) { \
        asm volatile("{\n\t.reg .pred P1;\n\tWL_%=:\n\tmbarrier.try_wait.parity.acquire.cta.shared::cta.b64 P1, [%0], %1, 0x989680;\n\t@P1 bra.uni WD_%=;\n\tbra.uni WL_%=;\n\tWD_%=:\n\t}" \
            :: "r"(_m), "r"(_p) : "memory"); \
    } } while (0)

__device__ __forceinline__ void mma_f16(float* d, uint32_t a0, uint32_t a1,
                                        uint32_t a2, uint32_t a3,
                                        uint32_t b0, uint32_t b1) {
    asm volatile(
        "mma.sync.aligned.m16n8k16.row.col.f32.f16.f16.f32 "
        "{%0,%1,%2,%3}, {%4,%5,%6,%7}, {%8,%9}, {%0,%1,%2,%3};"
        : "+f"(d[0]), "+f"(d[1]), "+f"(d[2]), "+f"(d[3])
        : "r"(a0), "r"(a1), "r"(a2), "r"(a3), "r"(b0), "r"(b1));
}

// Packed-fp16 A&S-7.1.26 erf core, fp32 combine (validated R11).
__device__ __forceinline__ float2 gelu2(float v0, float v1) {
    const __half2 hA   = __float2half2_rn(0.3275911f);
    const __half2 hONE = __float2half2_rn(1.0f);
    const __half2 hC1  = __float2half2_rn(0.254829592f);
    const __half2 hC2  = __float2half2_rn(-0.284496736f);
    const __half2 hC3  = __float2half2_rn(1.421413741f);
    const __half2 hC4  = __float2half2_rn(-1.453152027f);
    const __half2 hC5  = __float2half2_rn(1.061405429f);
    float z0 = fabsf(v0) * 0.70710678118654752440f;
    float z1 = fabsf(v1) * 0.70710678118654752440f;
    __half2 zh = __floats2half2_rn(z0, z1);
    __half2 t  = h2rcp(__hfma2(hA, zh, hONE));
    __half2 p  = __hfma2(hC5, t, hC4);
    p = __hfma2(p, t, hC3);
    p = __hfma2(p, t, hC2);
    p = __hfma2(p, t, hC1);
    p = __hmul2(p, t);
    __half2 e  = h2exp(__hneg2(__hmul2(zh, zh)));
    __half2 er = __hfma2(__hneg2(p), e, hONE);
    float2 ef = __half22float2(er);
    float h0 = 0.5f * v0, h1 = 0.5f * v1;
    float2 r;
    r.x = fmaf(copysignf(ef.x, v0), h0, h0);
    r.y = fmaf(copysignf(ef.y, v1), h1, h1);
    return r;
}

__device__ __forceinline__ uint32_t smem_u32(const void* p) {
    uint32_t a;
    asm("{ .reg .u64 t; cvta.to.shared.u64 t, %1; cvt.u32.u64 %0, t; }" : "=r"(a) : "l"(p));
    return a;
}

// ---------------- prepass: A fp32 -> fp16 ----------------
__global__ void pggcn_prep(const float* __restrict__ A) {
    int i = blockIdx.x * 256 + threadIdx.x;
    float2 v = ((const float2*)A)[i];
    ((__half2*)g_A_h)[i] = __floats2half2_rn(v.x, v.y);
}

// ---------------- main fused kernel ----------------
__global__ __launch_bounds__(NTHREADS, 1)
void pggcn_main(const float* __restrict__ x,     // [B,N,T,F]
                const float* __restrict__ W,     // [HID,F]
                const float* __restrict__ bias,  // [HID]
                float* __restrict__ out)         // [B,N,T,HID]
{
    extern __shared__ __half smh[];
    const uint32_t sbase = smem_u32(smh);

    const int tid = threadIdx.x;
    const int wid = tid >> 5;    // 0..15
    const int lid = tid & 31;
    const int lq  = lid >> 2;
    const int lr  = lid & 3;
    const int b   = blockIdx.y;
    const int t0  = blockIdx.x * TT;

    const int m_base = (wid & 3) * 32;    // 4m x 4n warp grid
    const int n_base = (wid >> 2) * 64;

    const int la_row = ((lid >> 3) & 1) * 8 + (lid & 7);
    const int la_k   = (lid >> 4) * 8;
    const int lb_row = ((lid >> 4) & 1) * 8 + (lid & 7);
    const int lb_k   = ((lid >> 3) & 1) * 8;

    // mbarriers: free[0..2], fill[0..2]
    const uint32_t mb_free = sbase + OFF_MBAR_BYTES;
    const uint32_t mb_fill = sbase + OFF_MBAR_BYTES + 24;

    // ---- one-time fills: W (fp16), bias, mbarrier init
    {
#pragma unroll
        for (int it = 0; it < 2; it++) {
            int idx = it * NTHREADS + tid;
            int h = idx >> 4, wq = idx & 15;
            uint32_t w = packh2(W[h * FSZ + 2 * wq], W[h * FSZ + 2 * wq + 1]);
            *(uint32_t*)(smh + OFF_W + h * WS + 2 * wq) = w;
        }
        if (tid < HID) ((float*)((char*)smh + OFF_BIAS_BYTES))[tid] = bias[tid];
        if (tid == 0) {
#pragma unroll
            for (int s = 0; s < NSTG; s++) {
                MBAR_INIT(mb_free + s * 8, 16);
                MBAR_INIT(mb_fill + s * 8, 16);
            }
        }
    }

    float acc[2][8][4];
#pragma unroll
    for (int i = 0; i < 2; i++)
#pragma unroll
        for (int j = 0; j < 8; j++)
#pragma unroll
            for (int k = 0; k < 4; k++) acc[i][j][k] = 0.0f;

    const uint32_t aA = sbase + 2 * ((m_base + la_row) * SA + la_k);
    const uint32_t aB = sbase + 2 * (OFF_BX + (n_base + lb_row) * SB + lb_k);

    // fill roles
    const __half* Ah = (const __half*)g_A_h;
    const bool bact = (tid < BROWS);
    const int bn  = tid;
    const int btl = bn >> 5;
    const int bf  = bn & 31;
    const int bts = t0 - 4 + btl;
    const size_t RS = (size_t)TSZ * FSZ;
    const float* xbase = x + ((size_t)b * NSZ) * RS + (size_t)(bts < 0 ? 0 : bts) * FSZ + bf;

    float bpf[16];

    // ---- prologue: fill chunk 0 into stage 0, arrive fill[0], one block barrier
    {
#pragma unroll
        for (int it = 0; it < 3; it++) {
            int idx = it * NTHREADS + tid;
            if (idx < 1280) {
                int lag = idx >> 8, r8 = idx & 255;
                int i = r8 >> 1, hh = r8 & 1;
                const __half* src = Ah + (((size_t)(b * LAGS + lag) * NSZ) + i) * NSZ
                                       + hh * 8;
                uint32_t dst = sbase + 2 * (lag * A5_LAG + i * SA + hh * 8);
                CP_ASYNC16(dst, src);
            }
        }
        asm volatile("cp.async.commit_group;" ::: "memory");
        if (bact) {
            if (bts >= 0) {
#pragma unroll
                for (int p = 0; p < 16; p++) bpf[p] = xbase[(size_t)p * RS];
            } else {
#pragma unroll
                for (int p = 0; p < 16; p++) bpf[p] = 0.0f;
            }
            uint4* dst = (uint4*)(smh + OFF_BX + bn * SB);
            dst[0] = make_uint4(packh2(bpf[0], bpf[1]),  packh2(bpf[2], bpf[3]),
                                packh2(bpf[4], bpf[5]),  packh2(bpf[6], bpf[7]));
            dst[1] = make_uint4(packh2(bpf[8], bpf[9]),  packh2(bpf[10], bpf[11]),
                                packh2(bpf[12], bpf[13]), packh2(bpf[14], bpf[15]));
        }
        asm volatile("cp.async.wait_group 0;" ::: "memory");
    }
    __syncthreads();
    if (lid == 0) MBAR_ARRIVE(mb_fill + 0);   // uniform fill-parity bookkeeping

    // ---- 3-stage mbarrier pipeline: warps may skew up to ~2 chunks
    for (int jc = 0; jc < NCHUNK; jc++) {
        const int sc = jc % NSTG;
        const int jf = jc + 1;
        const int sf = jf % NSTG;
        const bool more = (jf < NCHUNK);
        const int j1 = jf * JC;

        // early global B loads for chunk jf (registers only)
        if (more && bact && bts >= 0) {
            const float* xb = xbase + (size_t)j1 * RS;
#pragma unroll
            for (int p = 0; p < 16; p++) bpf[p] = xb[(size_t)p * RS];
        }

        // fill stage sf with chunk jf's A
        if (more) {
            if (jf >= NSTG)
                MBAR_WAIT(mb_free + sf * 8, (uint32_t)((jf / NSTG - 1) & 1));
#pragma unroll
            for (int it = 0; it < 3; it++) {
                int idx = it * NTHREADS + tid;
                if (idx < 1280) {
                    int lag = idx >> 8, r8 = idx & 255;
                    int i = r8 >> 1, hh = r8 & 1;
                    const __half* src = Ah + (((size_t)(b * LAGS + lag) * NSZ) + i) * NSZ
                                           + j1 + hh * 8;
                    uint32_t dst = sbase + sf * ST_BYTES
                                 + 2 * (lag * A5_LAG + i * SA + hh * 8);
                    CP_ASYNC16(dst, src);
                }
            }
            asm volatile("cp.async.commit_group;" ::: "memory");
        }

        // chunk jc's fills all landed? (jc=0 passes immediately via prologue)
        MBAR_WAIT(mb_fill + sc * 8, (uint32_t)((jc / NSTG) & 1));

        // ---- compute chunk jc from stage sc (verbatim R14/R15)
        const uint32_t stB = sc * ST_BYTES;
#pragma unroll
        for (int lag = 0; lag < LAGS; lag++) {
            const uint32_t aL = aA + stB + lag * (A5_LAG * 2);
            const uint32_t bL = aB + stB + (4 - lag) * (32 * SB * 2);
            uint32_t a0[4], a1[4];
            LDSM_X4(a0[0], a0[1], a0[2], a0[3], aL);
            LDSM_X4(a1[0], a1[1], a1[2], a1[3], aL + 16 * SA * 2);
#pragma unroll
            for (int nf2 = 0; nf2 < 4; nf2++) {
                uint32_t bb[4];
                LDSM_X4(bb[0], bb[1], bb[2], bb[3], bL + nf2 * (16 * SB * 2));
                mma_f16(acc[0][2 * nf2],     a0[0], a0[1], a0[2], a0[3], bb[0], bb[1]);
                mma_f16(acc[0][2 * nf2 + 1], a0[0], a0[1], a0[2], a0[3], bb[2], bb[3]);
                mma_f16(acc[1][2 * nf2],     a1[0], a1[1], a1[2], a1[3], bb[0], bb[1]);
                mma_f16(acc[1][2 * nf2 + 1], a1[0], a1[1], a1[2], a1[3], bb[2], bb[3]);
            }
        }
        if (lid == 0) MBAR_ARRIVE(mb_free + sc * 8);

        // ---- finish fill of stage sf: drain own cp.asyncs + B STS, signal
        if (more) {
            asm volatile("cp.async.wait_group 0;" ::: "memory");
            if (bact) {
                uint4* dst = (uint4*)(smh + sf * ST + OFF_BX + bn * SB);
                if (bts >= 0) {
                    dst[0] = make_uint4(packh2(bpf[0], bpf[1]),  packh2(bpf[2], bpf[3]),
                                        packh2(bpf[4], bpf[5]),  packh2(bpf[6], bpf[7]));
                    dst[1] = make_uint4(packh2(bpf[8], bpf[9]),  packh2(bpf[10], bpf[11]),
                                        packh2(bpf[12], bpf[13]), packh2(bpf[14], bpf[15]));
                } else {
                    dst[0] = make_uint4(0u, 0u, 0u, 0u);
                    dst[1] = make_uint4(0u, 0u, 0u, 0u);
                }
            }
            if (lid == 0) MBAR_ARRIVE(mb_fill + sf * 8);
        }
    }

    // ---- stage 2 + epilogue: entirely from registers (verbatim R14/R15) ----
    {
        const uint32_t wB = sbase + 2 * (OFF_W + lb_row * WS + lb_k);
        const float* bias_s = (const float*)((char*)smh + OFF_BIAS_BYTES);
        const int tbase = (wid >> 2) * 2;

#pragma unroll
        for (int tg = 0; tg < 2; tg++) {
            uint32_t af[2][2][4];
#pragma unroll
            for (int kg = 0; kg < 2; kg++) {
                const int nfA = tg * 4 + kg * 2;
#pragma unroll
                for (int mf = 0; mf < 2; mf++) {
                    af[kg][mf][0] = packh2(acc[mf][nfA][0],     acc[mf][nfA][1]);
                    af[kg][mf][1] = packh2(acc[mf][nfA][2],     acc[mf][nfA][3]);
                    af[kg][mf][2] = packh2(acc[mf][nfA + 1][0], acc[mf][nfA + 1][1]);
                    af[kg][mf][3] = packh2(acc[mf][nfA + 1][2], acc[mf][nfA + 1][3]);
                }
            }

            float a2[2][8][4];
#pragma unroll
            for (int ho = 0; ho < 8; ho++) {
                const int h = ho * 8 + 2 * lr;
                const float bx = bias_s[h], by = bias_s[h + 1];
#pragma unroll
                for (int mf = 0; mf < 2; mf++) {
                    a2[mf][ho][0] = bx; a2[mf][ho][1] = by;
                    a2[mf][ho][2] = bx; a2[mf][ho][3] = by;
                }
            }

#pragma unroll
            for (int kg = 0; kg < 2; kg++) {
#pragma unroll
                for (int hq = 0; hq < 4; hq++) {
                    uint32_t wv[4];
                    LDSM_X4(wv[0], wv[1], wv[2], wv[3],
                            wB + hq * 16 * (WS * 2) + kg * 32);
#pragma unroll
                    for (int mf = 0; mf < 2; mf++) {
                        mma_f16(a2[mf][2 * hq],
                                af[kg][mf][0], af[kg][mf][1], af[kg][mf][2], af[kg][mf][3],
                                wv[0], wv[1]);
                        mma_f16(a2[mf][2 * hq + 1],
                                af[kg][mf][0], af[kg][mf][1], af[kg][mf][2], af[kg][mf][3],
                                wv[2], wv[3]);
                    }
                }
            }

            float* outB = out + (((size_t)b * NSZ) * TSZ + (t0 + tbase + tg)) * HID;
#pragma unroll
            for (int mf = 0; mf < 2; mf++) {
#pragma unroll
                for (int ho = 0; ho < 8; ho++) {
                    int r = m_base + mf * 16 + lq;
                    int h = ho * 8 + 2 * lr;
                    float2 o0 = gelu2(a2[mf][ho][0], a2[mf][ho][1]);
                    float2 o1 = gelu2(a2[mf][ho][2], a2[mf][ho][3]);
                    *(float2*)(outB + (size_t)r * (TSZ * HID) + h)       = o0;
                    *(float2*)(outB + (size_t)(r + 8) * (TSZ * HID) + h) = o1;
                }
            }
        }
    }
}

extern "C" void kernel_launch(void* const* d_in, const int* in_sizes, int n_in,
                              void* d_out, int out_size)
{
    const float* x    = (const float*)d_in[0];   // [8,128,2048,32]
    const float* A    = (const float*)d_in[1];   // [8,5,128,128]
    const float* W    = (const float*)d_in[2];   // [64,32]
    const float* bias = (const float*)d_in[3];   // [64]
    float* out = (float*)d_out;                  // [8,128,2048,64]
    (void)in_sizes; (void)n_in; (void)out_size;

    cudaFuncSetAttribute(pggcn_main,
                         cudaFuncAttributeMaxDynamicSharedMemorySize, SMEM_BYTES);

    pggcn_prep<<<1280, 256>>>(A);
    dim3 grid(TSZ / TT, BSZ);   // (256, 8)
    pggcn_main<<<grid, NTHREADS, SMEM_BYTES>>>(x, W, bias, out);
}